// round 8
// baseline (speedup 1.0000x reference)
#include <cuda_runtime.h>
#include <stdint.h>

#define KTAPS 27
#define SELF_K 13        // (0,0,0) offset: pair_in == row, mask == 1 always
#define CCH 64
#define TILE 32          // rows per block
#define THREADS 256      // 8 threads per row, 2 float4 per thread

// cfg: [0]=mask_kind (0 = 4-byte nonzero test, 1 = 2-byte/bf16 nonzero test)
//      [1]=mask_slot  [2]=pin_slot  [3]=pin_width (4 or 8)
__device__ int g_cfg[4];

#define F32_ONE   0x3F800000u
#define BF16_ONE  0x3F80

// ---------------- fused probe + decide (single block) ----------------
__global__ void kprobe_decide(const void* c0, const void* c1, const void* c2, int N)
{
    const void* cand[3] = {c0, c1, c2};
    __shared__ unsigned sc[3][5];
    const int t = threadIdx.x;
    if (t < 15) ((unsigned*)sc)[t] = 0u;
    __syncthreads();

    unsigned acc[3][5];
    #pragma unroll
    for (int s = 0; s < 3; s++)
        #pragma unroll
        for (int i = 0; i < 5; i++) acc[s][i] = 0u;

    // 2048 samples per slot, all inside tap 0 (N >= 2048).
    #pragma unroll
    for (int it = 0; it < 8; it++) {
        const unsigned e = (unsigned)(it * 256 + t);
        #pragma unroll
        for (int s = 0; s < 3; s++) {
            const unsigned w = ((const unsigned*)cand[s])[e];
            const uint16_t h = (uint16_t)(w & 0xFFFFu);
            const bool maskpat = (w == 0u) || (w == 1u) || (w == F32_ONE) ||
                                 (w == 0x3F803F80u) || (w == 0x00003F80u);
            acc[s][0] += !maskpat;
            acc[s][1] += (w == 1u);
            acc[s][2] += (h == BF16_ONE);
            acc[s][3] += (w != 0u && w != e);      // tap0: pair_out == e
        }
    }
    // self-tap arange check (i32 view), elements 13*N + t
    #pragma unroll
    for (int s = 0; s < 3; s++) {
        const unsigned a = ((const unsigned*)cand[s])[13u * (unsigned)N + (unsigned)t];
        acc[s][4] += (a != (unsigned)t);
    }

    const int lane = t & 31;
    #pragma unroll
    for (int s = 0; s < 3; s++)
        #pragma unroll
        for (int i = 0; i < 5; i++) {
            unsigned v = __reduce_add_sync(0xFFFFFFFFu, acc[s][i]);
            if (lane == 0 && v) atomicAdd(&sc[s][i], v);
        }
    __syncthreads();

    if (t == 0) {
        int ms = -1;
        for (int s = 0; s < 3; s++)
            if (sc[s][0] == 0 && ms < 0) ms = s;
        if (ms < 0) ms = 2;
        int mk = (sc[ms][1] == 0 && sc[ms][2] > 0) ? 1 : 0;
        int pa = -1, pb = -1;
        for (int s = 0; s < 3; s++) if (s != ms) { if (pa < 0) pa = s; else pb = s; }
        int pw  = (sc[pa][4] == 0 && sc[pb][4] == 0) ? 4 : 8;
        int pin = (sc[pa][3] >= sc[pb][3]) ? pa : pb;
        g_cfg[0] = mk; g_cfg[1] = ms; g_cfg[2] = pin; g_cfg[3] = pw;
    }
}

// ---------------- main kernel ----------------
__global__ __launch_bounds__(THREADS)
void spdwconv_kernel(const float* __restrict__ features,
                     const float* __restrict__ weight,   // [27*64], L1-resident
                     const float* __restrict__ bias,     // [64]
                     const void* c0, const void* c1, const void* c2,
                     float* __restrict__ out,
                     int n)
{
    __shared__ int      pin_s[KTAPS][TILE];   // written ONLY where mask set
    __shared__ unsigned bits_s[TILE];         // NEIGHBOR taps only (bit13 never set)

    const void* cand[3] = {c0, c1, c2};
    const int   mk    = g_cfg[0];
    const void* maskp = cand[g_cfg[1] & 3];
    const int   pw    = g_cfg[3];
    const void* pinp  = cand[g_cfg[2] & 3];

    const int t  = threadIdx.x;
    const int n0 = blockIdx.x * TILE;

    if (t < TILE) bits_s[t] = 0u;
    __syncthreads();

    // Stage ONLY the 26 neighbor taps (self tap handled unconditionally below:
    // its mask is always 1 and its index is the row itself).
    if (mk == 0 && (n & 3) == 0 && n0 + TILE <= n) {
        // Fast path: 26 taps * 8 quads = 208 work items, single pass.
        if (t < 26 * (TILE / 4)) {
            const int kk = t >> 3;                   // 0..25
            const int k  = kk + (kk >= SELF_K);      // skip 13
            const int q  = t & 7;
            const size_t base = (size_t)k * (size_t)n + (size_t)(n0 + q * 4);
            const uint4 mv = __ldcs((const uint4*)((const unsigned*)maskp + base));
            const int r0 = q * 4;
            if (mv.x) {
                pin_s[k][r0 + 0] = (pw == 4) ? __ldcs((const int*)pinp + base + 0)
                                             : (int)__ldcs((const long long*)pinp + base + 0);
                atomicOr(&bits_s[r0 + 0], 1u << k);
            }
            if (mv.y) {
                pin_s[k][r0 + 1] = (pw == 4) ? __ldcs((const int*)pinp + base + 1)
                                             : (int)__ldcs((const long long*)pinp + base + 1);
                atomicOr(&bits_s[r0 + 1], 1u << k);
            }
            if (mv.z) {
                pin_s[k][r0 + 2] = (pw == 4) ? __ldcs((const int*)pinp + base + 2)
                                             : (int)__ldcs((const long long*)pinp + base + 2);
                atomicOr(&bits_s[r0 + 2], 1u << k);
            }
            if (mv.w) {
                pin_s[k][r0 + 3] = (pw == 4) ? __ldcs((const int*)pinp + base + 3)
                                             : (int)__ldcs((const long long*)pinp + base + 3);
                atomicOr(&bits_s[r0 + 3], 1u << k);
            }
        }
    } else {
        // Scalar fallback (2-byte mask / unaligned / tail block).
        for (int i = t; i < 26 * TILE; i += THREADS) {
            const int kk = i / TILE;
            const int k  = kk + (kk >= SELF_K);
            const int r  = i - kk * TILE;
            const int nn = n0 + r;
            if (nn < n) {
                const size_t off = (size_t)k * (size_t)n + (size_t)nn;
                const bool m = (mk == 0)
                    ? (__ldcs((const unsigned*)maskp + off) != 0u)
                    : (__ldcs((const unsigned short*)maskp + off) != 0);
                if (m) {
                    pin_s[k][r] = (pw == 4) ? __ldcs((const int*)pinp + off)
                                            : (int)__ldcs((const long long*)pinp + off);
                    atomicOr(&bits_s[r], 1u << k);
                }
            }
        }
    }
    __syncthreads();

    const int r  = t >> 3;        // row within tile (0..31)
    const int c8 = t & 7;         // pair-of-float4 channel group
    const int nn = n0 + r;
    if (nn >= n) return;

    // Self tap: unconditional, fully coalesced feature read; uniform w13.
    const float4* fself = reinterpret_cast<const float4*>(features) + (size_t)nn * 16 + c8 * 2;
    const float4* w13   = reinterpret_cast<const float4*>(weight) + SELF_K * 16 + c8 * 2;
    const float4 sf0 = fself[0];
    const float4 sf1 = fself[1];
    const float4 sw0 = w13[0];
    const float4 sw1 = w13[1];
    float4 acc0 = reinterpret_cast<const float4*>(bias)[c8 * 2 + 0];
    float4 acc1 = reinterpret_cast<const float4*>(bias)[c8 * 2 + 1];

    unsigned b = bits_s[r];       // neighbor taps only (avg ~0.36 set bits)

    // Deterministic order: accumulate taps in ascending k. Self tap (k=13)
    // is merged at its ordered position via the bit-split below.
    unsigned blo = b & ((1u << SELF_K) - 1u);   // taps 0..12
    unsigned bhi = b >> (SELF_K + 1);           // taps 14..26 (shifted)

    while (blo) {
        const int k = __ffs(blo) - 1;
        blo &= blo - 1;
        const int j = pin_s[k][r];
        const float4* frow = reinterpret_cast<const float4*>(features) + (size_t)j * 16 + c8 * 2;
        const float4* wrow = reinterpret_cast<const float4*>(weight) + k * 16 + c8 * 2;
        const float4 fv0 = frow[0], fv1 = frow[1];
        const float4 wv0 = wrow[0], wv1 = wrow[1];
        acc0.x = fmaf(fv0.x, wv0.x, acc0.x); acc0.y = fmaf(fv0.y, wv0.y, acc0.y);
        acc0.z = fmaf(fv0.z, wv0.z, acc0.z); acc0.w = fmaf(fv0.w, wv0.w, acc0.w);
        acc1.x = fmaf(fv1.x, wv1.x, acc1.x); acc1.y = fmaf(fv1.y, wv1.y, acc1.y);
        acc1.z = fmaf(fv1.z, wv1.z, acc1.z); acc1.w = fmaf(fv1.w, wv1.w, acc1.w);
    }

    // self tap at k = 13
    acc0.x = fmaf(sf0.x, sw0.x, acc0.x); acc0.y = fmaf(sf0.y, sw0.y, acc0.y);
    acc0.z = fmaf(sf0.z, sw0.z, acc0.z); acc0.w = fmaf(sf0.w, sw0.w, acc0.w);
    acc1.x = fmaf(sf1.x, sw1.x, acc1.x); acc1.y = fmaf(sf1.y, sw1.y, acc1.y);
    acc1.z = fmaf(sf1.z, sw1.z, acc1.z); acc1.w = fmaf(sf1.w, sw1.w, acc1.w);

    while (bhi) {
        const int kb = __ffs(bhi) - 1;
        bhi &= bhi - 1;
        const int k = kb + SELF_K + 1;
        const int j = pin_s[k][r];
        const float4* frow = reinterpret_cast<const float4*>(features) + (size_t)j * 16 + c8 * 2;
        const float4* wrow = reinterpret_cast<const float4*>(weight) + k * 16 + c8 * 2;
        const float4 fv0 = frow[0], fv1 = frow[1];
        const float4 wv0 = wrow[0], wv1 = wrow[1];
        acc0.x = fmaf(fv0.x, wv0.x, acc0.x); acc0.y = fmaf(fv0.y, wv0.y, acc0.y);
        acc0.z = fmaf(fv0.z, wv0.z, acc0.z); acc0.w = fmaf(fv0.w, wv0.w, acc0.w);
        acc1.x = fmaf(fv1.x, wv1.x, acc1.x); acc1.y = fmaf(fv1.y, wv1.y, acc1.y);
        acc1.z = fmaf(fv1.z, wv1.z, acc1.z); acc1.w = fmaf(fv1.w, wv1.w, acc1.w);
    }

    // Output is write-once: stream it past L2.
    float4* orow = reinterpret_cast<float4*>(out) + (size_t)nn * 16 + c8 * 2;
    __stcs(orow + 0, acc0);
    __stcs(orow + 1, acc1);
}

extern "C" void kernel_launch(void* const* d_in, const int* in_sizes, int n_in,
                              void* d_out, int out_size)
{
    int fi = -1, wi = -1, bi = -1;
    int big[3], nbig = 0;
    long long maxc = -1;
    for (int i = 0; i < n_in; i++)
        if ((long long)in_sizes[i] > maxc) { maxc = in_sizes[i]; fi = i; }
    for (int i = 0; i < n_in; i++) {
        if (i == fi) continue;
        if (in_sizes[i] == 64) bi = i;
        else if (in_sizes[i] == KTAPS * CCH) wi = i;
        else if (nbig < 3) big[nbig++] = i;
    }
    const float* features = (const float*)d_in[fi];
    const float* weight   = (const float*)d_in[wi];
    const float* bias     = (const float*)d_in[bi];
    const void*  c0 = d_in[big[0]];
    const void*  c1 = d_in[big[1]];
    const void*  c2 = d_in[big[2]];
    float* out = (float*)d_out;

    const int n = in_sizes[fi] / CCH;

    kprobe_decide<<<1, 256>>>(c0, c1, c2, n);

    const int grid = (n + TILE - 1) / TILE;
    spdwconv_kernel<<<grid, THREADS>>>(features, weight, bias, c0, c1, c2, out, n);
}

// round 9
// speedup vs baseline: 1.1232x; 1.1232x over previous
#include <cuda_runtime.h>
#include <stdint.h>

#define KTAPS 27
#define SELF_K 13        // (0,0,0) offset: pair_in == row, mask == 1 always
#define CCH 64
#define TILE 16          // rows per block
#define THREADS 256      // 16 threads per row, one float4 per thread

// cfg: [0]=mask_kind (0 = 4-byte nonzero test, 1 = 2-byte/bf16 nonzero test)
//      [1]=mask_slot  [2]=pin_slot  [3]=pin_width (4 or 8)
__device__ int g_cfg[4];

#define F32_ONE   0x3F800000u
#define BF16_ONE  0x3F80

// ---------------- fused probe + decide (single block) ----------------
__global__ void kprobe_decide(const void* c0, const void* c1, const void* c2, int N)
{
    const void* cand[3] = {c0, c1, c2};
    __shared__ unsigned sc[3][5];
    const int t = threadIdx.x;
    if (t < 15) ((unsigned*)sc)[t] = 0u;
    __syncthreads();

    unsigned acc[3][5];
    #pragma unroll
    for (int s = 0; s < 3; s++)
        #pragma unroll
        for (int i = 0; i < 5; i++) acc[s][i] = 0u;

    // 2048 samples per slot, all inside tap 0 (N >= 2048).
    #pragma unroll
    for (int it = 0; it < 8; it++) {
        const unsigned e = (unsigned)(it * 256 + t);
        #pragma unroll
        for (int s = 0; s < 3; s++) {
            const unsigned w = ((const unsigned*)cand[s])[e];
            const uint16_t h = (uint16_t)(w & 0xFFFFu);
            const bool maskpat = (w == 0u) || (w == 1u) || (w == F32_ONE) ||
                                 (w == 0x3F803F80u) || (w == 0x00003F80u);
            acc[s][0] += !maskpat;
            acc[s][1] += (w == 1u);
            acc[s][2] += (h == BF16_ONE);
            acc[s][3] += (w != 0u && w != e);      // tap0: pair_out == e
        }
    }
    // self-tap arange check (i32 view), elements 13*N + t
    #pragma unroll
    for (int s = 0; s < 3; s++) {
        const unsigned a = ((const unsigned*)cand[s])[13u * (unsigned)N + (unsigned)t];
        acc[s][4] += (a != (unsigned)t);
    }

    const int lane = t & 31;
    #pragma unroll
    for (int s = 0; s < 3; s++)
        #pragma unroll
        for (int i = 0; i < 5; i++) {
            unsigned v = __reduce_add_sync(0xFFFFFFFFu, acc[s][i]);
            if (lane == 0 && v) atomicAdd(&sc[s][i], v);
        }
    __syncthreads();

    if (t == 0) {
        int ms = -1;
        for (int s = 0; s < 3; s++)
            if (sc[s][0] == 0 && ms < 0) ms = s;
        if (ms < 0) ms = 2;
        int mk = (sc[ms][1] == 0 && sc[ms][2] > 0) ? 1 : 0;
        int pa = -1, pb = -1;
        for (int s = 0; s < 3; s++) if (s != ms) { if (pa < 0) pa = s; else pb = s; }
        int pw  = (sc[pa][4] == 0 && sc[pb][4] == 0) ? 4 : 8;
        int pin = (sc[pa][3] >= sc[pb][3]) ? pa : pb;
        g_cfg[0] = mk; g_cfg[1] = ms; g_cfg[2] = pin; g_cfg[3] = pw;
    }
}

// ---------------- main kernel ----------------
__global__ __launch_bounds__(THREADS)
void spdwconv_kernel(const float* __restrict__ features,
                     const float* __restrict__ weight,   // [27*64], L1-resident
                     const float* __restrict__ bias,     // [64]
                     const void* c0, const void* c1, const void* c2,
                     float* __restrict__ out,
                     int n)
{
    __shared__ int      pin_s[KTAPS][TILE];   // written ONLY where mask set
    __shared__ unsigned bits_s[TILE];         // NEIGHBOR taps only (bit13 never set)

    const void* cand[3] = {c0, c1, c2};
    const int   mk    = g_cfg[0];
    const void* maskp = cand[g_cfg[1] & 3];
    const int   pw    = g_cfg[3];
    const void* pinp  = cand[g_cfg[2] & 3];

    const int t  = threadIdx.x;
    const int n0 = blockIdx.x * TILE;

    if (t < TILE) bits_s[t] = 0u;
    __syncthreads();

    // Stage ONLY the 26 neighbor taps (self tap handled unconditionally below).
    if (mk == 0 && (n & 3) == 0 && n0 + TILE <= n) {
        // Fast path: 26 taps * 4 quads = 104 work items, single pass.
        if (t < 26 * (TILE / 4)) {
            const int kk = t >> 2;                   // 0..25
            const int k  = kk + (kk >= SELF_K);      // skip 13
            const int q  = t & 3;
            const size_t base = (size_t)k * (size_t)n + (size_t)(n0 + q * 4);
            const uint4 mv = __ldcs((const uint4*)((const unsigned*)maskp + base));
            const int r0 = q * 4;
            if (mv.x) {
                pin_s[k][r0 + 0] = (pw == 4) ? __ldcs((const int*)pinp + base + 0)
                                             : (int)__ldcs((const long long*)pinp + base + 0);
                atomicOr(&bits_s[r0 + 0], 1u << k);
            }
            if (mv.y) {
                pin_s[k][r0 + 1] = (pw == 4) ? __ldcs((const int*)pinp + base + 1)
                                             : (int)__ldcs((const long long*)pinp + base + 1);
                atomicOr(&bits_s[r0 + 1], 1u << k);
            }
            if (mv.z) {
                pin_s[k][r0 + 2] = (pw == 4) ? __ldcs((const int*)pinp + base + 2)
                                             : (int)__ldcs((const long long*)pinp + base + 2);
                atomicOr(&bits_s[r0 + 2], 1u << k);
            }
            if (mv.w) {
                pin_s[k][r0 + 3] = (pw == 4) ? __ldcs((const int*)pinp + base + 3)
                                             : (int)__ldcs((const long long*)pinp + base + 3);
                atomicOr(&bits_s[r0 + 3], 1u << k);
            }
        }
    } else {
        // Scalar fallback (2-byte mask / unaligned / tail block).
        for (int i = t; i < 26 * TILE; i += THREADS) {
            const int kk = i >> 4;                   // TILE == 16
            const int k  = kk + (kk >= SELF_K);
            const int r  = i & 15;
            const int nn = n0 + r;
            if (nn < n) {
                const size_t off = (size_t)k * (size_t)n + (size_t)nn;
                const bool m = (mk == 0)
                    ? (__ldcs((const unsigned*)maskp + off) != 0u)
                    : (__ldcs((const unsigned short*)maskp + off) != 0);
                if (m) {
                    pin_s[k][r] = (pw == 4) ? __ldcs((const int*)pinp + off)
                                            : (int)__ldcs((const long long*)pinp + off);
                    atomicOr(&bits_s[r], 1u << k);
                }
            }
        }
    }
    __syncthreads();

    const int r  = t >> 4;        // row within tile (0..15)
    const int c4 = t & 15;        // float4 channel group
    const int nn = n0 + r;
    if (nn >= n) return;

    float4 acc = reinterpret_cast<const float4*>(bias)[c4];
    const unsigned b = bits_s[r];           // neighbor taps (avg ~0.36 set)
    unsigned blo = b & ((1u << SELF_K) - 1u);
    unsigned bhi = b >> (SELF_K + 1);

    // taps 0..12 (ascending, deterministic)
    while (blo) {
        const int k = __ffs(blo) - 1;
        blo &= blo - 1;
        const int j = pin_s[k][r];
        const float4 fv = reinterpret_cast<const float4*>(features)[(size_t)j * 16 + c4];
        const float4 wv = reinterpret_cast<const float4*>(weight)[k * 16 + c4];
        acc.x = fmaf(fv.x, wv.x, acc.x);
        acc.y = fmaf(fv.y, wv.y, acc.y);
        acc.z = fmaf(fv.z, wv.z, acc.z);
        acc.w = fmaf(fv.w, wv.w, acc.w);
    }

    // self tap (k = 13): coalesced feature read, loads issued HERE (not
    // hoisted) so they stay transient — R8's reg blowup came from hoisting.
    {
        const float4 fv = reinterpret_cast<const float4*>(features)[(size_t)nn * 16 + c4];
        const float4 wv = reinterpret_cast<const float4*>(weight)[SELF_K * 16 + c4];
        acc.x = fmaf(fv.x, wv.x, acc.x);
        acc.y = fmaf(fv.y, wv.y, acc.y);
        acc.z = fmaf(fv.z, wv.z, acc.z);
        acc.w = fmaf(fv.w, wv.w, acc.w);
    }

    // taps 14..26
    while (bhi) {
        const int kb = __ffs(bhi) - 1;
        bhi &= bhi - 1;
        const int k = kb + SELF_K + 1;
        const int j = pin_s[k][r];
        const float4 fv = reinterpret_cast<const float4*>(features)[(size_t)j * 16 + c4];
        const float4 wv = reinterpret_cast<const float4*>(weight)[k * 16 + c4];
        acc.x = fmaf(fv.x, wv.x, acc.x);
        acc.y = fmaf(fv.y, wv.y, acc.y);
        acc.z = fmaf(fv.z, wv.z, acc.z);
        acc.w = fmaf(fv.w, wv.w, acc.w);
    }

    // Output is write-once: stream it past L2.
    __stcs(reinterpret_cast<float4*>(out) + (size_t)nn * 16 + c4, acc);
}

extern "C" void kernel_launch(void* const* d_in, const int* in_sizes, int n_in,
                              void* d_out, int out_size)
{
    int fi = -1, wi = -1, bi = -1;
    int big[3], nbig = 0;
    long long maxc = -1;
    for (int i = 0; i < n_in; i++)
        if ((long long)in_sizes[i] > maxc) { maxc = in_sizes[i]; fi = i; }
    for (int i = 0; i < n_in; i++) {
        if (i == fi) continue;
        if (in_sizes[i] == 64) bi = i;
        else if (in_sizes[i] == KTAPS * CCH) wi = i;
        else if (nbig < 3) big[nbig++] = i;
    }
    const float* features = (const float*)d_in[fi];
    const float* weight   = (const float*)d_in[wi];
    const float* bias     = (const float*)d_in[bi];
    const void*  c0 = d_in[big[0]];
    const void*  c1 = d_in[big[1]];
    const void*  c2 = d_in[big[2]];
    float* out = (float*)d_out;

    const int n = in_sizes[fi] / CCH;

    kprobe_decide<<<1, 256>>>(c0, c1, c2, n);

    const int grid = (n + TILE - 1) / TILE;
    spdwconv_kernel<<<grid, THREADS>>>(features, weight, bias, c0, c1, c2, out, n);
}

// round 10
// speedup vs baseline: 1.2194x; 1.0857x over previous
#include <cuda_runtime.h>
#include <stdint.h>

#define KTAPS 27
#define SELF_K 13        // (0,0,0) offset: pair_in == row, mask == 1 always
#define CCH 64
#define TILE 16          // rows per block in main kernel
#define THREADS 256
#define MAXN 1048576     // scratch capacity (rows)

// cfg: [0]=mask_kind (0 = 4-byte nonzero test, 1 = 2-byte/bf16 nonzero test)
//      [1]=mask_slot  [2]=pin_slot  [3]=pin_width (4 or 8)
__device__ int g_cfg[4];
__device__ unsigned g_bits[MAXN];   // per-row neighbor-tap bitmask (bit13 unused)

#define F32_ONE   0x3F800000u
#define BF16_ONE  0x3F80

// ---------------- fused probe + decide (single block) ----------------
__global__ void kprobe_decide(const void* c0, const void* c1, const void* c2, int N)
{
    const void* cand[3] = {c0, c1, c2};
    __shared__ unsigned sc[3][5];
    const int t = threadIdx.x;
    if (t < 15) ((unsigned*)sc)[t] = 0u;
    __syncthreads();

    unsigned acc[3][5];
    #pragma unroll
    for (int s = 0; s < 3; s++)
        #pragma unroll
        for (int i = 0; i < 5; i++) acc[s][i] = 0u;

    #pragma unroll
    for (int it = 0; it < 8; it++) {
        const unsigned e = (unsigned)(it * 256 + t);
        #pragma unroll
        for (int s = 0; s < 3; s++) {
            const unsigned w = ((const unsigned*)cand[s])[e];
            const uint16_t h = (uint16_t)(w & 0xFFFFu);
            const bool maskpat = (w == 0u) || (w == 1u) || (w == F32_ONE) ||
                                 (w == 0x3F803F80u) || (w == 0x00003F80u);
            acc[s][0] += !maskpat;
            acc[s][1] += (w == 1u);
            acc[s][2] += (h == BF16_ONE);
            acc[s][3] += (w != 0u && w != e);      // tap0: pair_out == e
        }
    }
    #pragma unroll
    for (int s = 0; s < 3; s++) {
        const unsigned a = ((const unsigned*)cand[s])[13u * (unsigned)N + (unsigned)t];
        acc[s][4] += (a != (unsigned)t);
    }

    const int lane = t & 31;
    #pragma unroll
    for (int s = 0; s < 3; s++)
        #pragma unroll
        for (int i = 0; i < 5; i++) {
            unsigned v = __reduce_add_sync(0xFFFFFFFFu, acc[s][i]);
            if (lane == 0 && v) atomicAdd(&sc[s][i], v);
        }
    __syncthreads();

    if (t == 0) {
        int ms = -1;
        for (int s = 0; s < 3; s++)
            if (sc[s][0] == 0 && ms < 0) ms = s;
        if (ms < 0) ms = 2;
        int mk = (sc[ms][1] == 0 && sc[ms][2] > 0) ? 1 : 0;
        int pa = -1, pb = -1;
        for (int s = 0; s < 3; s++) if (s != ms) { if (pa < 0) pa = s; else pb = s; }
        int pw  = (sc[pa][4] == 0 && sc[pb][4] == 0) ? 4 : 8;
        int pin = (sc[pa][3] >= sc[pb][3]) ? pa : pb;
        g_cfg[0] = mk; g_cfg[1] = ms; g_cfg[2] = pin; g_cfg[3] = pw;
    }
}

// ---------------- mask -> bitmask precompute ----------------
// One thread per row; 26 independent fully-coalesced strided loads (MLP=26),
// one coalesced bitmask store. Pure streaming, runs at BW limit.
__global__ __launch_bounds__(256)
void kbits(const void* c0, const void* c1, const void* c2, int n)
{
    const void* cand[3] = {c0, c1, c2};
    const int   mk    = g_cfg[0];
    const void* maskp = cand[g_cfg[1] & 3];

    const int row = blockIdx.x * 256 + threadIdx.x;
    if (row >= n) return;

    unsigned bits = 0u;
    if (mk == 0) {
        const unsigned* m32 = (const unsigned*)maskp;
        #pragma unroll
        for (int kk = 0; kk < 26; kk++) {
            const int k = kk + (kk >= SELF_K);
            if (__ldcs(m32 + (size_t)k * (size_t)n + row)) bits |= 1u << k;
        }
    } else {
        const unsigned short* m16 = (const unsigned short*)maskp;
        #pragma unroll
        for (int kk = 0; kk < 26; kk++) {
            const int k = kk + (kk >= SELF_K);
            if (__ldcs(m16 + (size_t)k * (size_t)n + row)) bits |= 1u << k;
        }
    }
    g_bits[row] = bits;
}

// ---------------- main kernel: no smem, no barriers, no atomics ----------------
__global__ __launch_bounds__(THREADS)
void spdwconv_kernel(const float* __restrict__ features,
                     const float* __restrict__ weight,   // [27*64], L1-resident
                     const float* __restrict__ bias,     // [64]
                     const void* c0, const void* c1, const void* c2,
                     float* __restrict__ out,
                     int n)
{
    const void* cand[3] = {c0, c1, c2};
    const int   pw   = g_cfg[3];
    const void* pinp = cand[g_cfg[2] & 3];

    const int t  = threadIdx.x;
    const int r  = t >> 4;        // row within tile (0..15)
    const int c4 = t & 15;        // float4 channel group
    const int nn = blockIdx.x * TILE + r;
    if (nn >= n) return;

    const unsigned b = g_bits[nn];          // broadcast across the half-warp
    float4 acc = reinterpret_cast<const float4*>(bias)[c4];
    unsigned blo = b & ((1u << SELF_K) - 1u);
    unsigned bhi = b >> (SELF_K + 1);

    // taps 0..12 (ascending, deterministic)
    while (blo) {
        const int k = __ffs(blo) - 1;
        blo &= blo - 1;
        const int j = (pw == 4)
            ? __ldg((const int*)pinp + (size_t)k * (size_t)n + nn)
            : (int)__ldg((const long long*)pinp + (size_t)k * (size_t)n + nn);
        const float4 fv = reinterpret_cast<const float4*>(features)[(size_t)j * 16 + c4];
        const float4 wv = reinterpret_cast<const float4*>(weight)[k * 16 + c4];
        acc.x = fmaf(fv.x, wv.x, acc.x);
        acc.y = fmaf(fv.y, wv.y, acc.y);
        acc.z = fmaf(fv.z, wv.z, acc.z);
        acc.w = fmaf(fv.w, wv.w, acc.w);
    }

    // self tap (k = 13): coalesced feature read, transient registers only
    {
        const float4 fv = reinterpret_cast<const float4*>(features)[(size_t)nn * 16 + c4];
        const float4 wv = reinterpret_cast<const float4*>(weight)[SELF_K * 16 + c4];
        acc.x = fmaf(fv.x, wv.x, acc.x);
        acc.y = fmaf(fv.y, wv.y, acc.y);
        acc.z = fmaf(fv.z, wv.z, acc.z);
        acc.w = fmaf(fv.w, wv.w, acc.w);
    }

    // taps 14..26
    while (bhi) {
        const int kb = __ffs(bhi) - 1;
        bhi &= bhi - 1;
        const int k = kb + SELF_K + 1;
        const int j = (pw == 4)
            ? __ldg((const int*)pinp + (size_t)k * (size_t)n + nn)
            : (int)__ldg((const long long*)pinp + (size_t)k * (size_t)n + nn);
        const float4 fv = reinterpret_cast<const float4*>(features)[(size_t)j * 16 + c4];
        const float4 wv = reinterpret_cast<const float4*>(weight)[k * 16 + c4];
        acc.x = fmaf(fv.x, wv.x, acc.x);
        acc.y = fmaf(fv.y, wv.y, acc.y);
        acc.z = fmaf(fv.z, wv.z, acc.z);
        acc.w = fmaf(fv.w, wv.w, acc.w);
    }

    // Output is write-once: stream it past L2.
    __stcs(reinterpret_cast<float4*>(out) + (size_t)nn * 16 + c4, acc);
}

extern "C" void kernel_launch(void* const* d_in, const int* in_sizes, int n_in,
                              void* d_out, int out_size)
{
    int fi = -1, wi = -1, bi = -1;
    int big[3], nbig = 0;
    long long maxc = -1;
    for (int i = 0; i < n_in; i++)
        if ((long long)in_sizes[i] > maxc) { maxc = in_sizes[i]; fi = i; }
    for (int i = 0; i < n_in; i++) {
        if (i == fi) continue;
        if (in_sizes[i] == 64) bi = i;
        else if (in_sizes[i] == KTAPS * CCH) wi = i;
        else if (nbig < 3) big[nbig++] = i;
    }
    const float* features = (const float*)d_in[fi];
    const float* weight   = (const float*)d_in[wi];
    const float* bias     = (const float*)d_in[bi];
    const void*  c0 = d_in[big[0]];
    const void*  c1 = d_in[big[1]];
    const void*  c2 = d_in[big[2]];
    float* out = (float*)d_out;

    const int n = in_sizes[fi] / CCH;

    kprobe_decide<<<1, 256>>>(c0, c1, c2, n);
    kbits<<<(n + 255) / 256, 256>>>(c0, c1, c2, n);

    const int grid = (n + TILE - 1) / TILE;
    spdwconv_kernel<<<grid, THREADS>>>(features, weight, bias, c0, c1, c2, out, n);
}